// round 5
// baseline (speedup 1.0000x reference)
#include <cuda_runtime.h>

#define NPTS 4096
#define NB   8
#define KNN  20
#define CO   64
#define CTA  256
#define SLOTS 16            // keys per thread
#define TIE_CAP 64
#define HBITS 11
#define HBINS (1 << HBITS)  // 2048
#define HSHIFT (32 - HBITS) // 21

__device__ float4 g_xp[NB * NPTS];   // {x, y, z, -0.5*|p|^2}
__device__ float4 g_wf[CO * 2];      // per o: {w0,w1,w2,w3}, {w4,w5,inv,shift}

__global__ void prep_kernel(const float* __restrict__ x)
{
    int idx = blockIdx.x * blockDim.x + threadIdx.x;
    if (idx >= NB * NPTS) return;
    int b = idx >> 12, p = idx & (NPTS - 1);
    const float* xb = x + (size_t)b * 3 * NPTS;
    float px = xb[p], py = xb[NPTS + p], pz = xb[2 * NPTS + p];
    g_xp[idx] = make_float4(px, py, pz, -0.5f * (px*px + py*py + pz*pz));
}

__global__ void prep_params(const float* __restrict__ W,
                            const float* __restrict__ gamma_,
                            const float* __restrict__ beta_,
                            const float* __restrict__ mean_,
                            const float* __restrict__ var_)
{
    int o = threadIdx.x;
    if (o < CO) {
        float inv   = gamma_[o] * rsqrtf(var_[o] + 1e-5f);
        float shift = beta_[o] - mean_[o] * inv;
        g_wf[2*o]   = make_float4(W[6*o+0], W[6*o+1], W[6*o+2], W[6*o+3]);
        g_wf[2*o+1] = make_float4(W[6*o+4], W[6*o+5], inv, shift);
    }
}

__global__ __launch_bounds__(CTA, 6)
void edgeconv_kernel(float* __restrict__ out)
{
    __shared__ int      hist[HBINS];
    __shared__ int      warpTot[8], warpOff[8];
    __shared__ int      knn_s[KNN];
    __shared__ float4   nbr[KNN];
    __shared__ int      tie_idx[TIE_CAP];
    __shared__ unsigned tie_key[TIE_CAP];
    __shared__ int      s_cntW, s_cntT, s_need, s_cnt, s_shift;
    __shared__ unsigned s_prefix;

    const int b    = blockIdx.y;
    const int n    = blockIdx.x;
    const int tid  = threadIdx.x;
    const int lane = tid & 31;
    const int wid  = tid >> 5;
    unsigned lt_mask; asm("mov.u32 %0, %%lanemask_lt;" : "=r"(lt_mask));

    const float4* __restrict__ xp = g_xp + (size_t)b * NPTS;
    const float4 q = xp[n];

    #pragma unroll
    for (int i = 0; i < HBINS / CTA; i++) hist[i * CTA + tid] = 0;
    if (tid == 0) { s_cntW = 0; s_cntT = 0; s_need = KNN; s_cnt = 0; s_shift = HSHIFT; }
    __syncthreads();

    // ---- phase 1: keys (pd/2, monotone uint) in registers + 11-bit histogram
    unsigned ku[SLOTS];
    #pragma unroll
    for (int i = 0; i < SLOTS; i++) {
        float4 v = xp[i * CTA + tid];
        float s = q.w + v.w;
        s = fmaf(q.x, v.x, fmaf(q.y, v.y, fmaf(q.z, v.z, s)));
        unsigned bb = __float_as_uint(s);
        unsigned u  = bb ^ (unsigned)(((int)bb >> 31) | 0x80000000);
        ku[i] = u;
        int bin = (int)(u >> HSHIFT);
        unsigned mk = __match_any_sync(0xffffffffu, bin);
        if (!(mk & lt_mask)) atomicAdd(&hist[bin], __popc(mk));
    }
    __syncthreads();

    // ---- block-wide descending suffix scan over 2048 bins, select threshold bin
    {
        int base = HBINS - 1 - (tid << 3);
        int c[8]; int tsum = 0;
        #pragma unroll
        for (int j = 0; j < 8; j++) { c[j] = hist[base - j]; tsum += c[j]; }
        int cum = tsum;
        #pragma unroll
        for (int off = 1; off < 32; off <<= 1) {
            int t = __shfl_up_sync(0xffffffffu, cum, off);
            if (lane >= off) cum += t;
        }
        if (lane == 31) warpTot[wid] = cum;
        __syncthreads();
        if (wid == 0) {
            int v = (lane < 8) ? warpTot[lane] : 0;
            int cc = v;
            #pragma unroll
            for (int off = 1; off < 8; off <<= 1) {
                int t = __shfl_up_sync(0xffffffffu, cc, off);
                if (lane >= off) cc += t;
            }
            if (lane < 8) warpOff[lane] = cc - v;
        }
        __syncthreads();
        int cumAll    = cum + warpOff[wid];
        int cumBefore = cumAll - tsum;
        if (cumBefore < KNN && KNN <= cumAll) {
            int acc = cumBefore;
            #pragma unroll
            for (int j = 0; j < 8; j++) {
                if (acc + c[j] >= KNN) {
                    s_prefix = (unsigned)(base - j);
                    s_need   = KNN - acc;
                    s_cnt    = c[j];
                    break;
                }
                acc += c[j];
            }
        }
    }
    __syncthreads();

    // ---- rare fallback: refine threshold bin by 8 more bits at a time
    while (s_cnt > TIE_CAP && s_shift > 0) {
        if (tid < 256) hist[tid] = 0;
        __syncthreads();
        const unsigned pf = s_prefix;
        const int sh  = s_shift;
        const int nsh = (sh >= 8) ? sh - 8 : 0;
        #pragma unroll
        for (int i = 0; i < SLOTS; i++) {
            unsigned u = ku[i];
            bool valid = (u >> sh) == pf;
            int bin = valid ? (int)((u >> nsh) & 255u) : -1;
            unsigned mk = __match_any_sync(0xffffffffu, bin);
            if (valid && !(mk & lt_mask)) atomicAdd(&hist[bin], __popc(mk));
        }
        __syncthreads();
        if (wid == 0) {
            int base = 255 - lane * 8;
            int c[8]; int ssum = 0;
            #pragma unroll
            for (int j = 0; j < 8; j++) { c[j] = hist[base - j]; ssum += c[j]; }
            int cum = ssum;
            #pragma unroll
            for (int off = 1; off < 32; off <<= 1) {
                int t = __shfl_up_sync(0xffffffffu, cum, off);
                if (lane >= off) cum += t;
            }
            int needv = s_need;
            int cumBefore = cum - ssum;
            if (cumBefore < needv && needv <= cum) {
                int acc = cumBefore;
                #pragma unroll
                for (int j = 0; j < 8; j++) {
                    if (acc + c[j] >= needv) {
                        s_prefix = (pf << 8) | (unsigned)(base - j);
                        s_need   = needv - acc;
                        s_cnt    = c[j];
                        s_shift  = nsh;
                        break;
                    }
                    acc += c[j];
                }
            }
        }
        __syncthreads();
    }

    // ---- collect winners (unordered set) + boundary-bin tie candidates
    {
        const int      sh = s_shift;
        const unsigned pf = s_prefix;
        #pragma unroll
        for (int i = 0; i < SLOTS; i++) {
            unsigned u  = ku[i];
            unsigned hi = u >> sh;
            if (hi >= pf) {
                if (hi > pf) {
                    knn_s[atomicAdd(&s_cntW, 1)] = i * CTA + tid;
                } else {
                    int pos = atomicAdd(&s_cntT, 1);
                    if (pos < TIE_CAP) { tie_idx[pos] = i * CTA + tid; tie_key[pos] = u; }
                }
            }
        }
    }
    __syncthreads();

    // ---- parallel exact tie resolve: rank by (value desc, index asc)
    {
        int cnt   = s_cntT < TIE_CAP ? s_cntT : TIE_CAP;
        int needf = s_need;
        int baseW = s_cntW;
        if (tid < cnt) {
            unsigned mk = tie_key[tid]; int mi = tie_idx[tid];
            int rank = 0;
            for (int j = 0; j < cnt; j++) {
                unsigned kj = tie_key[j]; int ij = tie_idx[j];
                rank += (kj > mk) || (kj == mk && ij < mi);
            }
            if (rank < needf) knn_s[baseW + rank] = mi;
        }
    }
    __syncthreads();

    // ---- gather neighbor coords
    if (tid < KNN) nbr[tid] = xp[knn_s[tid]];
    __syncthreads();

    // ---- edge MLP: 4 threads per output channel, 5 k's each, shfl-combine
    {
        const int o = tid >> 2;
        const int c = tid & 3;
        const float4 wa = g_wf[2*o];      // w0 w1 w2 w3
        const float4 wb = g_wf[2*o + 1];  // w4 w5 inv shift
        const float cpart = fmaf(q.x, wa.w, fmaf(q.y, wb.x, q.z * wb.y));

        float m = -3.4028235e38f;
        #pragma unroll
        for (int k = 0; k < 5; k++) {
            float4 p = nbr[c * 5 + k];
            float y = fmaf(p.x - q.x, wa.x,
                      fmaf(p.y - q.y, wa.y,
                      fmaf(p.z - q.z, wa.z, cpart)));
            y = fmaf(y, wb.z, wb.w);
            y = (y >= 0.0f) ? y : 0.2f * y;
            m = fmaxf(m, y);
        }
        m = fmaxf(m, __shfl_xor_sync(0xffffffffu, m, 1));
        m = fmaxf(m, __shfl_xor_sync(0xffffffffu, m, 2));
        if (c == 0)
            out[(size_t)b * CO * NPTS + (size_t)o * NPTS + n] = m;
    }
}

extern "C" void kernel_launch(void* const* d_in, const int* in_sizes, int n_in,
                              void* d_out, int out_size)
{
    const float* x      = (const float*)d_in[0];
    const float* W      = (const float*)d_in[1];
    const float* gamma_ = (const float*)d_in[2];
    const float* beta_  = (const float*)d_in[3];
    const float* mean_  = (const float*)d_in[4];
    const float* var_   = (const float*)d_in[5];
    float* out = (float*)d_out;

    prep_kernel<<<(NB * NPTS + 255) / 256, 256>>>(x);
    prep_params<<<1, 64>>>(W, gamma_, beta_, mean_, var_);
    dim3 grid(NPTS, NB);
    edgeconv_kernel<<<grid, CTA>>>(out);
}

// round 6
// speedup vs baseline: 1.3318x; 1.3318x over previous
#include <cuda_runtime.h>

#define NPTS 4096
#define NB   8
#define KNN  20
#define CO   64
#define CTA  512
#define SLOTS 8             // keys per thread
#define TIE_CAP 128
#define HBITS 12
#define HBINS (1 << HBITS)  // 4096
#define HSHIFT (32 - HBITS) // 20

__device__ float4 g_xp[NB * NPTS];   // {x, y, z, -0.5*|p|^2}
__device__ float4 g_wf[CO * 2];      // per o: {w0,w1,w2,w3}, {w4,w5,inv,shift}

__global__ void prep_kernel(const float* __restrict__ x,
                            const float* __restrict__ W,
                            const float* __restrict__ gamma_,
                            const float* __restrict__ beta_,
                            const float* __restrict__ mean_,
                            const float* __restrict__ var_)
{
    int idx = blockIdx.x * blockDim.x + threadIdx.x;
    if (idx < NB * NPTS) {
        int b = idx >> 12, p = idx & (NPTS - 1);
        const float* xb = x + (size_t)b * 3 * NPTS;
        float px = xb[p], py = xb[NPTS + p], pz = xb[2 * NPTS + p];
        g_xp[idx] = make_float4(px, py, pz, -0.5f * (px*px + py*py + pz*pz));
    }
    if (blockIdx.x == 0 && threadIdx.x < CO) {
        int o = threadIdx.x;
        float inv   = gamma_[o] * rsqrtf(var_[o] + 1e-5f);
        float shift = beta_[o] - mean_[o] * inv;
        g_wf[2*o]   = make_float4(W[6*o+0], W[6*o+1], W[6*o+2], W[6*o+3]);
        g_wf[2*o+1] = make_float4(W[6*o+4], W[6*o+5], inv, shift);
    }
}

__global__ __launch_bounds__(CTA, 3)
void edgeconv_kernel(float* __restrict__ out)
{
    __shared__ int      hist[HBINS];
    __shared__ int      warpTot[16], warpOff[16];
    __shared__ int      knn_s[KNN];
    __shared__ float4   nbr[KNN];
    __shared__ int      tie_idx[TIE_CAP];
    __shared__ unsigned tie_key[TIE_CAP];
    __shared__ int      s_cntW, s_cntT, s_need, s_cnt, s_shift;
    __shared__ unsigned s_prefix;

    const int b    = blockIdx.y;
    const int n    = blockIdx.x;
    const int tid  = threadIdx.x;
    const int lane = tid & 31;
    const int wid  = tid >> 5;

    const float4* __restrict__ xp = g_xp + (size_t)b * NPTS;
    const float4 q = xp[n];

    #pragma unroll
    for (int i = 0; i < HBINS / CTA; i++) hist[i * CTA + tid] = 0;
    if (tid == 0) { s_cntW = 0; s_cntT = 0; s_need = KNN; s_cnt = 0; s_shift = HSHIFT; }
    __syncthreads();

    // ---- phase 1: keys (pd/2 as monotone uint) in registers + 12-bit histogram
    unsigned ku[SLOTS];
    #pragma unroll
    for (int i = 0; i < SLOTS; i++) {
        float4 v = xp[i * CTA + tid];
        float s = q.w + v.w;
        s = fmaf(q.x, v.x, fmaf(q.y, v.y, fmaf(q.z, v.z, s)));
        unsigned bb = __float_as_uint(s);
        unsigned u  = bb ^ (unsigned)(((int)bb >> 31) | 0x80000000);
        ku[i] = u;
        atomicAdd(&hist[u >> HSHIFT], 1);
    }
    __syncthreads();

    // ---- block-wide descending suffix scan over 4096 bins, select threshold bin
    {
        int base = HBINS - 1 - (tid << 3);
        int c[8]; int tsum = 0;
        #pragma unroll
        for (int j = 0; j < 8; j++) { c[j] = hist[base - j]; tsum += c[j]; }
        int cum = tsum;
        #pragma unroll
        for (int off = 1; off < 32; off <<= 1) {
            int t = __shfl_up_sync(0xffffffffu, cum, off);
            if (lane >= off) cum += t;
        }
        if (lane == 31) warpTot[wid] = cum;
        __syncthreads();
        if (wid == 0) {
            int v = (lane < 16) ? warpTot[lane] : 0;
            int cc = v;
            #pragma unroll
            for (int off = 1; off < 16; off <<= 1) {
                int t = __shfl_up_sync(0xffffffffu, cc, off);
                if (lane >= off) cc += t;
            }
            if (lane < 16) warpOff[lane] = cc - v;
        }
        __syncthreads();
        int cumAll    = cum + warpOff[wid];
        int cumBefore = cumAll - tsum;
        if (cumBefore < KNN && KNN <= cumAll) {
            int acc = cumBefore;
            #pragma unroll
            for (int j = 0; j < 8; j++) {
                if (acc + c[j] >= KNN) {
                    s_prefix = (unsigned)(base - j);
                    s_need   = KNN - acc;
                    s_cnt    = c[j];
                    break;
                }
                acc += c[j];
            }
        }
    }
    __syncthreads();

    // ---- rare fallback: refine threshold bin by 8 more bits at a time
    while (s_cnt > TIE_CAP && s_shift > 0) {
        if (tid < 256) hist[tid] = 0;
        __syncthreads();
        const unsigned pf = s_prefix;
        const int sh  = s_shift;
        const int nsh = (sh >= 8) ? sh - 8 : 0;
        #pragma unroll
        for (int i = 0; i < SLOTS; i++) {
            unsigned u = ku[i];
            if ((u >> sh) == pf) atomicAdd(&hist[(u >> nsh) & 255u], 1);
        }
        __syncthreads();
        if (wid == 0) {
            int base = 255 - lane * 8;
            int c[8]; int ssum = 0;
            #pragma unroll
            for (int j = 0; j < 8; j++) { c[j] = hist[base - j]; ssum += c[j]; }
            int cum = ssum;
            #pragma unroll
            for (int off = 1; off < 32; off <<= 1) {
                int t = __shfl_up_sync(0xffffffffu, cum, off);
                if (lane >= off) cum += t;
            }
            int needv = s_need;
            int cumBefore = cum - ssum;
            if (cumBefore < needv && needv <= cum) {
                int acc = cumBefore;
                #pragma unroll
                for (int j = 0; j < 8; j++) {
                    if (acc + c[j] >= needv) {
                        s_prefix = (pf << 8) | (unsigned)(base - j);
                        s_need   = needv - acc;
                        s_cnt    = c[j];
                        s_shift  = nsh;
                        break;
                    }
                    acc += c[j];
                }
            }
        }
        __syncthreads();
    }

    // ---- collect winners (unordered set) + boundary-bin tie candidates
    {
        const int      sh = s_shift;
        const unsigned pf = s_prefix;
        #pragma unroll
        for (int i = 0; i < SLOTS; i++) {
            unsigned u  = ku[i];
            unsigned hi = u >> sh;
            if (hi >= pf) {
                if (hi > pf) {
                    knn_s[atomicAdd(&s_cntW, 1)] = i * CTA + tid;
                } else {
                    int pos = atomicAdd(&s_cntT, 1);
                    if (pos < TIE_CAP) { tie_idx[pos] = i * CTA + tid; tie_key[pos] = u; }
                }
            }
        }
    }
    __syncthreads();

    // ---- parallel exact tie resolve: rank by (value desc, index asc)
    {
        int cnt   = s_cntT < TIE_CAP ? s_cntT : TIE_CAP;
        int needf = s_need;
        int baseW = s_cntW;
        if (tid < cnt) {
            unsigned mk = tie_key[tid]; int mi = tie_idx[tid];
            int rank = 0;
            for (int j = 0; j < cnt; j++) {
                unsigned kj = tie_key[j]; int ij = tie_idx[j];
                rank += (kj > mk) || (kj == mk && ij < mi);
            }
            if (rank < needf) knn_s[baseW + rank] = mi;
        }
    }
    __syncthreads();

    // ---- gather neighbor coords
    if (tid < KNN) nbr[tid] = xp[knn_s[tid]];
    __syncthreads();

    // ---- edge MLP: 8 threads per output channel, strided k, shfl-combine
    {
        const int o = tid >> 3;
        const int c = tid & 7;
        const float4 wa = g_wf[2*o];      // w0 w1 w2 w3
        const float4 wb = g_wf[2*o + 1];  // w4 w5 inv shift
        const float cpart = fmaf(q.x, wa.w, fmaf(q.y, wb.x, q.z * wb.y));

        float m = -3.4028235e38f;
        #pragma unroll
        for (int k = c; k < KNN; k += 8) {
            float4 p = nbr[k];
            float y = fmaf(p.x - q.x, wa.x,
                      fmaf(p.y - q.y, wa.y,
                      fmaf(p.z - q.z, wa.z, cpart)));
            y = fmaf(y, wb.z, wb.w);
            y = (y >= 0.0f) ? y : 0.2f * y;
            m = fmaxf(m, y);
        }
        m = fmaxf(m, __shfl_xor_sync(0xffffffffu, m, 1));
        m = fmaxf(m, __shfl_xor_sync(0xffffffffu, m, 2));
        m = fmaxf(m, __shfl_xor_sync(0xffffffffu, m, 4));
        if (c == 0)
            out[(size_t)b * CO * NPTS + (size_t)o * NPTS + n] = m;
    }
}

extern "C" void kernel_launch(void* const* d_in, const int* in_sizes, int n_in,
                              void* d_out, int out_size)
{
    const float* x      = (const float*)d_in[0];
    const float* W      = (const float*)d_in[1];
    const float* gamma_ = (const float*)d_in[2];
    const float* beta_  = (const float*)d_in[3];
    const float* mean_  = (const float*)d_in[4];
    const float* var_   = (const float*)d_in[5];
    float* out = (float*)d_out;

    prep_kernel<<<(NB * NPTS + 255) / 256, 256>>>(x, W, gamma_, beta_, mean_, var_);
    dim3 grid(NPTS, NB);
    edgeconv_kernel<<<grid, CTA>>>(out);
}

// round 8
// speedup vs baseline: 1.6893x; 1.2685x over previous
#include <cuda_runtime.h>

#define NPTS 4096
#define NB   8
#define KNN  20
#define CO   64
#define CTA  256
#define SLOTS 16            // keys per thread (in smem)
#define TIE_CAP 128

__device__ float4 g_xp[NB * NPTS];   // {x, y, z, -0.5*|p|^2}
__device__ float4 g_wf[CO * 2];      // per o: {w0,w1,w2,w3}, {w4,w5,inv,shift}

__global__ void prep_kernel(const float* __restrict__ x,
                            const float* __restrict__ W,
                            const float* __restrict__ gamma_,
                            const float* __restrict__ beta_,
                            const float* __restrict__ mean_,
                            const float* __restrict__ var_)
{
    int idx = blockIdx.x * blockDim.x + threadIdx.x;
    if (idx < NB * NPTS) {
        int b = idx >> 12, p = idx & (NPTS - 1);
        const float* xb = x + (size_t)b * 3 * NPTS;
        float px = xb[p], py = xb[NPTS + p], pz = xb[2 * NPTS + p];
        g_xp[idx] = make_float4(px, py, pz, -0.5f * (px*px + py*py + pz*pz));
    }
    if (blockIdx.x == 0 && threadIdx.x < CO) {
        int o = threadIdx.x;
        float inv   = gamma_[o] * rsqrtf(var_[o] + 1e-5f);
        float shift = beta_[o] - mean_[o] * inv;
        g_wf[2*o]   = make_float4(W[6*o+0], W[6*o+1], W[6*o+2], W[6*o+3]);
        g_wf[2*o+1] = make_float4(W[6*o+4], W[6*o+5], inv, shift);
    }
}

__global__ __launch_bounds__(CTA)
void edgeconv_kernel(float* __restrict__ out)
{
    __shared__ unsigned keysu[NPTS];       // 16 KB
    __shared__ int      hist[256];
    __shared__ int      warpTot[8], warpOff[8];
    __shared__ int      knn_s[KNN];
    __shared__ float4   nbr[KNN];
    __shared__ int      tie_idx[TIE_CAP];
    __shared__ unsigned tie_key[TIE_CAP];
    __shared__ int      s_cntW, s_cntT, s_need, s_cnt, s_shift;
    __shared__ unsigned s_prefix;

    const int b    = blockIdx.y;
    const int n    = blockIdx.x;
    const int tid  = threadIdx.x;
    const int lane = tid & 31;
    const int wid  = tid >> 5;
    unsigned lt_mask; asm("mov.u32 %0, %%lanemask_lt;" : "=r"(lt_mask));

    const float4* __restrict__ xp = g_xp + (size_t)b * NPTS;
    const float4 q = xp[n];

    hist[tid] = 0;
    if (tid == 0) { s_cntW = 0; s_cntT = 0; s_need = KNN; s_cnt = 0; s_shift = 24; }
    __syncthreads();

    // ---- phase 1: keys (pd/2 as monotone uint) -> smem, warp-aggregated 256-bin hist
    #pragma unroll
    for (int i = 0; i < SLOTS; i++) {
        int p = i * CTA + tid;
        float4 v = xp[p];
        float s = q.w + v.w;
        s = fmaf(q.x, v.x, fmaf(q.y, v.y, fmaf(q.z, v.z, s)));
        unsigned bb = __float_as_uint(s);
        unsigned u  = bb ^ (unsigned)(((int)bb >> 31) | 0x80000000);
        keysu[p] = u;
        int bin = (int)(u >> 24);
        unsigned mk = __match_any_sync(0xffffffffu, bin);
        if (!(mk & lt_mask)) atomicAdd(&hist[bin], __popc(mk));
    }
    __syncthreads();

    // ---- block-wide descending suffix scan over 256 bins (1 bin per thread)
    // select uses the compile-time constant KNN -> no shared-state race.
    {
        int binv = hist[255 - tid];              // thread t owns bin 255-t
        int cum = binv;
        #pragma unroll
        for (int off = 1; off < 32; off <<= 1) {
            int t = __shfl_up_sync(0xffffffffu, cum, off);
            if (lane >= off) cum += t;
        }
        if (lane == 31) warpTot[wid] = cum;
        __syncthreads();
        if (wid == 0) {
            int v = (lane < 8) ? warpTot[lane] : 0;
            int cc = v;
            #pragma unroll
            for (int off = 1; off < 8; off <<= 1) {
                int t = __shfl_up_sync(0xffffffffu, cc, off);
                if (lane >= off) cc += t;
            }
            if (lane < 8) warpOff[lane] = cc - v;
        }
        __syncthreads();
        int cumAll    = cum + warpOff[wid];
        int cumBefore = cumAll - binv;
        if (cumBefore < KNN && KNN <= cumAll) {  // exactly one thread (binv>0 required)
            s_prefix = (unsigned)(255 - tid);
            s_need   = KNN - cumBefore;
            s_cnt    = binv;
        }
    }
    __syncthreads();

    // ---- fallback: refine threshold bin by 8 more bits at a time.
    // RACE FIX: snapshot shared state at loop top (stable since trailing barrier),
    // so the select condition is evaluated against a coherent needv everywhere.
    while (s_cnt > TIE_CAP && s_shift > 0) {
        const unsigned pf    = s_prefix;   // coherent snapshots
        const int      sh    = s_shift;
        const int      nsh   = sh - 8;
        const int      needv = s_need;
        __syncthreads();                   // everyone snapshotted before hist reuse
        hist[tid] = 0;
        __syncthreads();
        #pragma unroll
        for (int i = 0; i < SLOTS; i++) {
            unsigned u = keysu[i * CTA + tid];
            bool valid = (u >> sh) == pf;
            int bin = valid ? (int)((u >> nsh) & 255u) : -1;
            unsigned mk = __match_any_sync(0xffffffffu, bin);
            if (valid && !(mk & lt_mask)) atomicAdd(&hist[bin], __popc(mk));
        }
        __syncthreads();
        {
            int binv = hist[255 - tid];
            int cum = binv;
            #pragma unroll
            for (int off = 1; off < 32; off <<= 1) {
                int t = __shfl_up_sync(0xffffffffu, cum, off);
                if (lane >= off) cum += t;
            }
            if (lane == 31) warpTot[wid] = cum;
            __syncthreads();
            if (wid == 0) {
                int v = (lane < 8) ? warpTot[lane] : 0;
                int cc = v;
                #pragma unroll
                for (int off = 1; off < 8; off <<= 1) {
                    int t = __shfl_up_sync(0xffffffffu, cc, off);
                    if (lane >= off) cc += t;
                }
                if (lane < 8) warpOff[lane] = cc - v;
            }
            __syncthreads();
            int cumAll    = cum + warpOff[wid];
            int cumBefore = cumAll - binv;
            if (cumBefore < needv && needv <= cumAll) {   // needv is a pre-barrier snapshot
                s_prefix = (pf << 8) | (unsigned)(255 - tid);
                s_need   = needv - cumBefore;
                s_cnt    = binv;
                s_shift  = nsh;
            }
        }
        __syncthreads();
    }

    // ---- collect winners (unordered set) + boundary-bin tie candidates
    {
        const int      sh = s_shift;
        const unsigned pf = s_prefix;
        #pragma unroll
        for (int i = 0; i < SLOTS; i++) {
            int p = i * CTA + tid;
            unsigned u  = keysu[p];
            unsigned hi = u >> sh;
            if (hi >= pf) {
                if (hi > pf) {
                    knn_s[atomicAdd(&s_cntW, 1)] = p;
                } else {
                    int pos = atomicAdd(&s_cntT, 1);
                    if (pos < TIE_CAP) { tie_idx[pos] = p; tie_key[pos] = u; }
                }
            }
        }
    }
    __syncthreads();

    // ---- parallel exact tie resolve: rank by (value desc, index asc)
    {
        int cnt   = s_cntT < TIE_CAP ? s_cntT : TIE_CAP;
        int needf = s_need;
        int baseW = s_cntW;
        if (tid < cnt) {
            unsigned mk = tie_key[tid]; int mi = tie_idx[tid];
            int rank = 0;
            for (int j = 0; j < cnt; j++) {             // broadcast reads
                unsigned kj = tie_key[j]; int ij = tie_idx[j];
                rank += (kj > mk) || (kj == mk && ij < mi);
            }
            if (rank < needf) knn_s[baseW + rank] = mi;
        }
    }
    __syncthreads();

    // ---- gather neighbor coords
    if (tid < KNN) nbr[tid] = xp[knn_s[tid]];
    __syncthreads();

    // ---- edge MLP: 4 threads per output channel, 5 k's each, shfl-combine
    {
        const int o = tid >> 2;
        const int c = tid & 3;
        const float4 wa = g_wf[2*o];      // w0 w1 w2 w3
        const float4 wb = g_wf[2*o + 1];  // w4 w5 inv shift
        const float cpart = fmaf(q.x, wa.w, fmaf(q.y, wb.x, q.z * wb.y));

        float m = -3.4028235e38f;
        #pragma unroll
        for (int k = 0; k < 5; k++) {
            float4 p = nbr[c * 5 + k];
            float y = fmaf(p.x - q.x, wa.x,
                      fmaf(p.y - q.y, wa.y,
                      fmaf(p.z - q.z, wa.z, cpart)));
            y = fmaf(y, wb.z, wb.w);
            y = (y >= 0.0f) ? y : 0.2f * y;
            m = fmaxf(m, y);
        }
        m = fmaxf(m, __shfl_xor_sync(0xffffffffu, m, 1));
        m = fmaxf(m, __shfl_xor_sync(0xffffffffu, m, 2));
        if (c == 0)
            out[(size_t)b * CO * NPTS + (size_t)o * NPTS + n] = m;
    }
}

extern "C" void kernel_launch(void* const* d_in, const int* in_sizes, int n_in,
                              void* d_out, int out_size)
{
    const float* x      = (const float*)d_in[0];
    const float* W      = (const float*)d_in[1];
    const float* gamma_ = (const float*)d_in[2];
    const float* beta_  = (const float*)d_in[3];
    const float* mean_  = (const float*)d_in[4];
    const float* var_   = (const float*)d_in[5];
    float* out = (float*)d_out;

    prep_kernel<<<(NB * NPTS + 255) / 256, 256>>>(x, W, gamma_, beta_, mean_, var_);
    dim3 grid(NPTS, NB);
    edgeconv_kernel<<<grid, CTA>>>(out);
}